// round 15
// baseline (speedup 1.0000x reference)
#include <cuda_runtime.h>
#include <cuda_pipeline_primitives.h>

// PSRoIPool (R-FCN style), fp32.
// features: [B=4, C=490, H=38, W=38], rois: [R=256, 5], out: [R,10,7,7]
// c = (d*P + ph)*P + pw
//
// Numerics (locked, PASS @ rel_err 2.845666e-08):
//  - xs/ys/xe/ye exact (integer/16); bin = roi * RN(1/7) (XLA reciprocal-
//    multiply strength reduction, NOT fdiv)
//  - edges via fmaf; two-level ascending summation (rows of w, then h)
//
// Perf (R15): R12's staging loop (LDG->STS, thread-dependent trip count)
// was a SERIAL chain: ~6 x 600cyc latency exposures/block == the measured
// ~3.6k cyc/block x 3.3 blocks/SM == 6.9us. Replace with cp.async
// (LDGSTS): fire-and-forget, all ~6 copies in flight (MLP=6), one latency
// exposure. Window math (independent of smem) issues in the copy shadow.
// Block = channel c (490 blocks, single wave, every thread useful).

#define P_ 7
#define D_ 10
#define H_ 38
#define W_ 38
#define C_ 490
#define R_ 256
#define B_ 4
#define PLANE_ (H_ * W_)          // 1444 floats, 5776 B
#define PLANE4_ (PLANE_ / 4)      // 361 float4
#define SCALE_ 0.0625f

__global__ __launch_bounds__(256) void psroi_kernel(
    const float* __restrict__ feat,
    const float* __restrict__ rois,
    float* __restrict__ out)
{
    __shared__ float4 sf4[B_ * PLANE4_];         // 23104 B

    int c   = blockIdx.x;                        // 0..489, channel plane
    int tid = threadIdx.x;                       // 0..255 == ROI index

    // ---- async-stage feat[0..3][c][:,:] into smem (LDGSTS, MLP=6) ----
    const float4* src = (const float4*)feat;
    for (int k = tid; k < B_ * PLANE4_; k += 256) {
        int b = k / PLANE4_;
        int q = k - b * PLANE4_;
        __pipeline_memcpy_async(&sf4[k],
                                &src[((size_t)b * C_ + c) * PLANE4_ + q], 16);
    }
    __pipeline_commit();

    // ---- window math: independent of smem, hides under the copies ----
    const float* roi = rois + tid * 5;
    int b = (int)roi[0];

    int pw = c % P_;                // column bin (bin_w, xs)
    int ph = (c / P_) % P_;         // row bin    (bin_h, ys)

    // jnp.round == round-half-to-even == rintf (RN); *0.0625 exact
    float xs = __fmul_rn(rintf(roi[1]), SCALE_);
    float ys = __fmul_rn(rintf(roi[2]), SCALE_);
    float xe = __fmul_rn(rintf(__fadd_rn(roi[3], 1.0f)), SCALE_);
    float ye = __fmul_rn(rintf(__fadd_rn(roi[4], 1.0f)), SCALE_);

    const float RECIP7 = 1.0f / 7.0f;   // RN(1/7)
    float bin_w = __fmul_rn(fmaxf(__fadd_rn(xe, -xs), 0.1f), RECIP7);
    float bin_h = __fmul_rn(fmaxf(__fadd_rn(ye, -ys), 0.1f), RECIP7);

    // edges: single-rounding FMA; clip to [0,H]/[0,W]
    float hs = floorf(fmaf((float) ph,      bin_h, ys));
    float he = ceilf (fmaf((float)(ph + 1), bin_h, ys));
    float ws = floorf(fmaf((float) pw,      bin_w, xs));
    float we = ceilf (fmaf((float)(pw + 1), bin_w, xs));

    int hstart = (int)fminf(fmaxf(hs, 0.0f), (float)H_);
    int hend   = (int)fminf(fmaxf(he, 0.0f), (float)H_);
    int wstart = (int)fminf(fmaxf(ws, 0.0f), (float)W_);
    int wend   = (int)fminf(fmaxf(we, 0.0f), (float)W_);

    int hspan = hend - hstart;          // 0..4 (roi wh <= 256 -> span <= 4)
    int wspan = wend - wstart;          // 0..4

    __pipeline_wait_prior(0);
    __syncthreads();

    const float* base = (const float*)sf4 + b * PLANE_ + hstart * W_ + wstart;

    // predicated 4x4 gather from smem, exact two-level ascending reduce
    float v[4][4];
    #pragma unroll
    for (int i = 0; i < 4; ++i) {
        #pragma unroll
        for (int j = 0; j < 4; ++j) {
            bool valid = (i < hspan) && (j < wspan);
            v[i][j] = valid ? base[i * W_ + j] : 0.0f;
        }
    }

    float sum = 0.0f;
    #pragma unroll
    for (int i = 0; i < 4; ++i) {
        float rsum = 0.0f;
        #pragma unroll
        for (int j = 0; j < 4; ++j)
            rsum = __fadd_rn(rsum, v[i][j]);   // ascending w
        sum = __fadd_rn(sum, rsum);            // ascending h
    }

    int cnt = hspan * wspan;
    // out[r][d][ph][pw] = out[tid*490 + c]
    out[tid * C_ + c] = (cnt > 0) ? __fdiv_rn(sum, (float)cnt) : 0.0f;
}

extern "C" void kernel_launch(void* const* d_in, const int* in_sizes, int n_in,
                              void* d_out, int out_size)
{
    const float* feat = (const float*)d_in[0];
    const float* rois = (const float*)d_in[1];
    float* out = (float*)d_out;

    psroi_kernel<<<C_, 256>>>(feat, rois, out);   // 490 blocks, 1 ROI/thread
}

// round 16
// speedup vs baseline: 1.1179x; 1.1179x over previous
#include <cuda_runtime.h>
#include <cuda_pipeline_primitives.h>

// PSRoIPool (R-FCN style), fp32.
// features: [B=4, C=490, H=38, W=38], rois: [R=256, 5], out: [R,10,7,7]
// c = (d*P + ph)*P + pw
//
// Numerics (locked, PASS @ rel_err 2.845666e-08):
//  - xs/ys/xe/ye exact (integer/16); bin = roi * RN(1/7) (XLA reciprocal-
//    multiply strength reduction, NOT fdiv)
//  - edges via fmaf; two-level ascending summation (rows of w, then h)
//
// Perf (R16): R12-R15 all serialized [stage -> drain -> compute] per
// channel (ncu 6.7-6.9us vs ~2us BW floor). Double-buffered 2-channel
// pipeline: 245 blocks, both channels' cp.async issued up front (2x bytes
// in flight), roi constants computed once (channel-independent), and
// gather of c0 overlaps the drain of c1. Single wave, every SM occupied.

#define P_ 7
#define D_ 10
#define H_ 38
#define W_ 38
#define C_ 490
#define R_ 256
#define B_ 4
#define PLANE_ (H_ * W_)          // 1444 floats, 5776 B
#define PLANE4_ (PLANE_ / 4)      // 361 float4
#define SCALE_ 0.0625f

struct Win { int hstart, hend, wstart, wend; };

__device__ __forceinline__ Win make_win(int c, float xs, float ys,
                                        float bin_w, float bin_h)
{
    int pw = c % P_;
    int ph = (c / P_) % P_;
    // edges: single-rounding FMA; clip to [0,H]/[0,W]
    float hs = floorf(fmaf((float) ph,      bin_h, ys));
    float he = ceilf (fmaf((float)(ph + 1), bin_h, ys));
    float ws = floorf(fmaf((float) pw,      bin_w, xs));
    float we = ceilf (fmaf((float)(pw + 1), bin_w, xs));
    Win w;
    w.hstart = (int)fminf(fmaxf(hs, 0.0f), (float)H_);
    w.hend   = (int)fminf(fmaxf(he, 0.0f), (float)H_);
    w.wstart = (int)fminf(fmaxf(ws, 0.0f), (float)W_);
    w.wend   = (int)fminf(fmaxf(we, 0.0f), (float)W_);
    return w;
}

__device__ __forceinline__ float pool_win(const float* __restrict__ sf,
                                          int b, const Win& W)
{
    int hspan = W.hend - W.hstart;      // 0..4 (roi wh <= 256 -> span <= 4)
    int wspan = W.wend - W.wstart;      // 0..4
    const float* base = sf + b * PLANE_ + W.hstart * W_ + W.wstart;

    float v[4][4];
    #pragma unroll
    for (int i = 0; i < 4; ++i) {
        #pragma unroll
        for (int j = 0; j < 4; ++j) {
            bool valid = (i < hspan) && (j < wspan);
            v[i][j] = valid ? base[i * W_ + j] : 0.0f;
        }
    }
    float sum = 0.0f;
    #pragma unroll
    for (int i = 0; i < 4; ++i) {
        float rsum = 0.0f;
        #pragma unroll
        for (int j = 0; j < 4; ++j)
            rsum = __fadd_rn(rsum, v[i][j]);   // ascending w
        sum = __fadd_rn(sum, rsum);            // ascending h
    }
    int cnt = hspan * wspan;
    return (cnt > 0) ? __fdiv_rn(sum, (float)cnt) : 0.0f;
}

__global__ __launch_bounds__(256) void psroi_kernel(
    const float* __restrict__ feat,
    const float* __restrict__ rois,
    float* __restrict__ out)
{
    __shared__ float4 sf4[2][B_ * PLANE4_];      // 2 x 23104 B

    int tid = threadIdx.x;                       // 0..255 == ROI index
    int c0  = 2 * blockIdx.x;                    // adjacent channel pair
    int c1  = c0 + 1;

    // ---- async-stage both channels' 4 planes (fire-and-forget) ----
    const float4* src = (const float4*)feat;
    for (int k = tid; k < B_ * PLANE4_; k += 256) {
        int b = k / PLANE4_;
        int q = k - b * PLANE4_;
        __pipeline_memcpy_async(&sf4[0][k],
                                &src[((size_t)b * C_ + c0) * PLANE4_ + q], 16);
    }
    __pipeline_commit();
    for (int k = tid; k < B_ * PLANE4_; k += 256) {
        int b = k / PLANE4_;
        int q = k - b * PLANE4_;
        __pipeline_memcpy_async(&sf4[1][k],
                                &src[((size_t)b * C_ + c1) * PLANE4_ + q], 16);
    }
    __pipeline_commit();

    // ---- roi math in the copy shadow (channel-independent constants) ----
    const float* roi = rois + tid * 5;
    int b = (int)roi[0];

    // jnp.round == round-half-to-even == rintf (RN); *0.0625 exact
    float xs = __fmul_rn(rintf(roi[1]), SCALE_);
    float ys = __fmul_rn(rintf(roi[2]), SCALE_);
    float xe = __fmul_rn(rintf(__fadd_rn(roi[3], 1.0f)), SCALE_);
    float ye = __fmul_rn(rintf(__fadd_rn(roi[4], 1.0f)), SCALE_);

    const float RECIP7 = 1.0f / 7.0f;   // RN(1/7)
    float bin_w = __fmul_rn(fmaxf(__fadd_rn(xe, -xs), 0.1f), RECIP7);
    float bin_h = __fmul_rn(fmaxf(__fadd_rn(ye, -ys), 0.1f), RECIP7);

    Win w0 = make_win(c0, xs, ys, bin_w, bin_h);
    Win w1 = make_win(c1, xs, ys, bin_w, bin_h);

    // ---- channel 0: gather while channel 1 still drains ----
    __pipeline_wait_prior(1);
    __syncthreads();
    out[tid * C_ + c0] = pool_win((const float*)sf4[0], b, w0);

    // ---- channel 1 ----
    __pipeline_wait_prior(0);
    __syncthreads();
    out[tid * C_ + c1] = pool_win((const float*)sf4[1], b, w1);
}

extern "C" void kernel_launch(void* const* d_in, const int* in_sizes, int n_in,
                              void* d_out, int out_size)
{
    const float* feat = (const float*)d_in[0];
    const float* rois = (const float*)d_in[1];
    float* out = (float*)d_out;

    psroi_kernel<<<C_ / 2, 256>>>(feat, rois, out);   // 245 blocks, 1 wave
}